// round 2
// baseline (speedup 1.0000x reference)
#include <cuda_runtime.h>
#include <math.h>

// ---------------- problem constants ----------------
#define BB 4
#define NN 4096
#define DD 1024
#define HH 16
#define HD 64
#define MLP 4096
#define MM (BB*NN)          // 16384 rows

// ---------------- scratch (device globals; no allocation allowed) ------
__device__ float g_xn  [(size_t)MM * DD];
__device__ float g_q   [(size_t)MM * DD];
__device__ float g_k   [(size_t)MM * DD];
__device__ float g_v   [(size_t)MM * DD];
__device__ float g_attn[(size_t)MM * DD];
__device__ float g_x   [(size_t)MM * DD];
__device__ float g_h   [(size_t)MM * MLP];

// ---------------- LayerNorm (D=1024, biased var, eps=1e-5) -------------
__global__ __launch_bounds__(256) void ln_kernel(
    const float* __restrict__ X, const float* __restrict__ w,
    const float* __restrict__ b, float* __restrict__ Y)
{
    const int row = blockIdx.x;
    const int tid = threadIdx.x;
    const float* x = X + (size_t)row * DD;

    float4 xv = *(const float4*)(x + tid * 4);
    float s  = xv.x + xv.y + xv.z + xv.w;
    float s2 = fmaf(xv.x, xv.x, fmaf(xv.y, xv.y, fmaf(xv.z, xv.z, xv.w * xv.w)));

    #pragma unroll
    for (int o = 16; o; o >>= 1) {
        s  += __shfl_xor_sync(0xFFFFFFFFu, s,  o);
        s2 += __shfl_xor_sync(0xFFFFFFFFu, s2, o);
    }
    __shared__ float sh[8], sh2[8];
    const int lane = tid & 31, wid = tid >> 5;
    if (lane == 0) { sh[wid] = s; sh2[wid] = s2; }
    __syncthreads();
    float S = 0.f, S2 = 0.f;
    #pragma unroll
    for (int i = 0; i < 8; i++) { S += sh[i]; S2 += sh2[i]; }

    const float mean = S * (1.0f / DD);
    const float var  = S2 * (1.0f / DD) - mean * mean;
    const float inv  = rsqrtf(var + 1e-5f);

    float4 wv = *(const float4*)(w + tid * 4);
    float4 bv = *(const float4*)(b + tid * 4);
    float4 y;
    y.x = (xv.x - mean) * inv * wv.x + bv.x;
    y.y = (xv.y - mean) * inv * wv.y + bv.y;
    y.z = (xv.z - mean) * inv * wv.z + bv.z;
    y.w = (xv.w - mean) * inv * wv.w + bv.w;
    *(float4*)(Y + (size_t)row * DD + tid * 4) = y;
}

// ---------------- generic tiled GEMM: C = A[M,K] @ W[K,N] + bias (+epi) --
// EPI: 0 = bias only, 1 = bias + residual R, 2 = bias + exact GELU
#define BM 128
#define BN 128
#define BK 16

template<int EPI>
__global__ __launch_bounds__(256) void gemm_kernel(
    const float* __restrict__ A, const float* __restrict__ W,
    const float* __restrict__ bias, const float* __restrict__ R,
    float* __restrict__ C, int M, int N, int K)
{
    __shared__ float As[BK][BM];   // A tile, transposed (k-major)
    __shared__ float Ws[BK][BN];   // W tile

    const int tid = threadIdx.x;
    const int bm = blockIdx.y * BM;
    const int bn = blockIdx.x * BN;

    const int a_row = tid >> 2;          // 0..63 (x2 iterations)
    const int a_col = (tid & 3) * 4;     // 0,4,8,12
    const int w_row = tid >> 5;          // 0..7 (x2 iterations)
    const int w_col = (tid & 31) * 4;    // 0..124

    const int ty = tid >> 4;             // 0..15
    const int tx = tid & 15;             // 0..15

    float acc[8][8];
    #pragma unroll
    for (int i = 0; i < 8; i++)
        #pragma unroll
        for (int j = 0; j < 8; j++) acc[i][j] = 0.f;

    for (int k0 = 0; k0 < K; k0 += BK) {
        #pragma unroll
        for (int r = 0; r < 2; r++) {
            const int row = a_row + r * 64;
            float4 v = *(const float4*)(A + (size_t)(bm + row) * K + k0 + a_col);
            As[a_col + 0][row] = v.x;
            As[a_col + 1][row] = v.y;
            As[a_col + 2][row] = v.z;
            As[a_col + 3][row] = v.w;
        }
        #pragma unroll
        for (int r = 0; r < 2; r++) {
            const int row = w_row + r * 8;
            *(float4*)&Ws[row][w_col] =
                *(const float4*)(W + (size_t)(k0 + row) * N + bn + w_col);
        }
        __syncthreads();

        #pragma unroll
        for (int kk = 0; kk < BK; kk++) {
            float a[8], b[8];
            *(float4*)(a + 0) = *(const float4*)&As[kk][ty * 8 + 0];
            *(float4*)(a + 4) = *(const float4*)&As[kk][ty * 8 + 4];
            *(float4*)(b + 0) = *(const float4*)&Ws[kk][tx * 8 + 0];
            *(float4*)(b + 4) = *(const float4*)&Ws[kk][tx * 8 + 4];
            #pragma unroll
            for (int i = 0; i < 8; i++)
                #pragma unroll
                for (int j = 0; j < 8; j++)
                    acc[i][j] = fmaf(a[i], b[j], acc[i][j]);
        }
        __syncthreads();
    }

    // epilogue
    #pragma unroll
    for (int i = 0; i < 8; i++) {
        const int row = bm + ty * 8 + i;
        float* crow = C + (size_t)row * N + bn + tx * 8;
        const float* rrow = (EPI == 1) ? (R + (size_t)row * N + bn + tx * 8) : nullptr;
        float out[8];
        #pragma unroll
        for (int j = 0; j < 8; j++) {
            float vv = acc[i][j] + bias[bn + tx * 8 + j];
            if (EPI == 1) vv += rrow[j];
            if (EPI == 2) vv = 0.5f * vv * (1.0f + erff(vv * 0.70710678118654752f));
            out[j] = vv;
        }
        *(float4*)(crow + 0) = *(float4*)(out + 0);
        *(float4*)(crow + 4) = *(float4*)(out + 4);
    }
}

// ---------------- fused per-token linear attention ----------------
// The reference einsums reduce over the HEAD axis per position:
//   kv[d,e]  = sum_h fk[h,d] * v[h,e]        (64x64 per token)
//   qkv[h,e] = sum_d fq[h,d] * kv[d,e]
//   qk[h]    = sum_d fq[h,d] * ksum[d],  out = qkv/(qk+1e-6)
// One CTA per token; everything fits in SMEM.
__device__ __forceinline__ float elu1(float x) {
    return x > 0.f ? x + 1.0f : expf(x);   // elu(x)+1
}

__global__ __launch_bounds__(256) void attn_kernel(
    const float* __restrict__ Q, const float* __restrict__ K_,
    const float* __restrict__ V, float* __restrict__ O)
{
    __shared__ float fq[HH][HD];
    __shared__ float fk[HH][HD];
    __shared__ float vv[HH][HD];
    __shared__ float kv[HD][HD];
    __shared__ float ksum[HD];

    const size_t base = (size_t)blockIdx.x * DD;
    const int tid = threadIdx.x;

    // load + transform (1024 floats each; 256 threads x float4)
    {
        float4 q4 = *(const float4*)(Q  + base + tid * 4);
        float4 k4 = *(const float4*)(K_ + base + tid * 4);
        float4 v4 = *(const float4*)(V  + base + tid * 4);
        float* fqf = &fq[0][0];
        float* fkf = &fk[0][0];
        float* vvf = &vv[0][0];
        fqf[tid*4+0] = elu1(q4.x); fqf[tid*4+1] = elu1(q4.y);
        fqf[tid*4+2] = elu1(q4.z); fqf[tid*4+3] = elu1(q4.w);
        fkf[tid*4+0] = elu1(k4.x); fkf[tid*4+1] = elu1(k4.y);
        fkf[tid*4+2] = elu1(k4.z); fkf[tid*4+3] = elu1(k4.w);
        vvf[tid*4+0] = v4.x; vvf[tid*4+1] = v4.y;
        vvf[tid*4+2] = v4.z; vvf[tid*4+3] = v4.w;
    }
    __syncthreads();

    // ksum[d] = sum_h fk[h][d]
    if (tid < HD) {
        float s = 0.f;
        #pragma unroll
        for (int h = 0; h < HH; h++) s += fk[h][tid];
        ksum[tid] = s;
    }

    // kv[d][e] = sum_h fk[h][d] * v[h][e]
    {
        const int e = tid & 63;
        const int d0 = tid >> 6;       // 0..3
        #pragma unroll
        for (int j = 0; j < 16; j++) {
            const int d = d0 + j * 4;
            float s = 0.f;
            #pragma unroll
            for (int h = 0; h < HH; h++) s = fmaf(fk[h][d], vv[h][e], s);
            kv[d][e] = s;
        }
    }
    __syncthreads();

    // qkv / qk
    {
        const int e = tid & 63;
        const int h0 = tid >> 6;       // 0..3
        #pragma unroll
        for (int j = 0; j < 4; j++) {
            const int h = h0 + j * 4;
            float s = 0.f, sq = 0.f;
            #pragma unroll
            for (int d = 0; d < HD; d++) {
                const float f = fq[h][d];
                s  = fmaf(f, kv[d][e], s);
                sq = fmaf(f, ksum[d], sq);
            }
            O[base + h * HD + e] = s / (sq + 1e-6f);
        }
    }
}

// ---------------- launch ----------------
extern "C" void kernel_launch(void* const* d_in, const int* in_sizes, int n_in,
                              void* d_out, int out_size)
{
    const float* q_x    = (const float*)d_in[0];
    const float* ln1_w  = (const float*)d_in[1];
    const float* ln1_b  = (const float*)d_in[2];
    const float* wq     = (const float*)d_in[3];
    const float* bq     = (const float*)d_in[4];
    const float* wk     = (const float*)d_in[5];
    const float* bk     = (const float*)d_in[6];
    const float* wv     = (const float*)d_in[7];
    const float* bv     = (const float*)d_in[8];
    const float* wo     = (const float*)d_in[9];
    const float* bo     = (const float*)d_in[10];
    const float* ln2_w  = (const float*)d_in[11];
    const float* ln2_b  = (const float*)d_in[12];
    const float* fc_w   = (const float*)d_in[13];
    const float* fc_b   = (const float*)d_in[14];
    const float* proj_w = (const float*)d_in[15];
    const float* proj_b = (const float*)d_in[16];
    float* out = (float*)d_out;

    float *p_xn, *p_q, *p_k, *p_v, *p_attn, *p_x, *p_h;
    cudaGetSymbolAddress((void**)&p_xn,   g_xn);
    cudaGetSymbolAddress((void**)&p_q,    g_q);
    cudaGetSymbolAddress((void**)&p_k,    g_k);
    cudaGetSymbolAddress((void**)&p_v,    g_v);
    cudaGetSymbolAddress((void**)&p_attn, g_attn);
    cudaGetSymbolAddress((void**)&p_x,    g_x);
    cudaGetSymbolAddress((void**)&p_h,    g_h);

    const dim3 gD (DD  / BN, MM / BM);   // (8, 128)
    const dim3 gML(MLP / BN, MM / BM);   // (32, 128)

    // 1) xn = LN1(q_x)
    ln_kernel<<<MM, 256>>>(q_x, ln1_w, ln1_b, p_xn);
    // 2) q/k/v = xn @ w* + b*
    gemm_kernel<0><<<gD, 256>>>(p_xn, wq, bq, nullptr, p_q, MM, DD, DD);
    gemm_kernel<0><<<gD, 256>>>(p_xn, wk, bk, nullptr, p_k, MM, DD, DD);
    gemm_kernel<0><<<gD, 256>>>(p_xn, wv, bv, nullptr, p_v, MM, DD, DD);
    // 3) fused per-token linear attention
    attn_kernel<<<MM, 256>>>(p_q, p_k, p_v, p_attn);
    // 4) x = q_x + attn @ wo + bo
    gemm_kernel<1><<<gD, 256>>>(p_attn, wo, bo, q_x, p_x, MM, DD, DD);
    // 5) xn2 = LN2(x)
    ln_kernel<<<MM, 256>>>(p_x, ln2_w, ln2_b, p_xn);
    // 6) h = gelu(xn2 @ fc_w + fc_b)
    gemm_kernel<2><<<gML, 256>>>(p_xn, fc_w, fc_b, nullptr, p_h, MM, MLP, DD);
    // 7) out = x + h @ proj_w + proj_b
    gemm_kernel<1><<<gD, 256>>>(p_h, proj_w, proj_b, p_x, out, MM, DD, MLP);
}

// round 3
// speedup vs baseline: 1.0009x; 1.0009x over previous
#include <cuda_runtime.h>
#include <math.h>

// ---------------- problem constants ----------------
#define BB 4
#define NN 4096
#define DD 1024
#define HH 16
#define HD 64
#define MLP 4096
#define MM (BB*NN)          // 16384 rows

// ---------------- scratch (device globals; no allocation allowed) ------
__device__ float g_xn  [(size_t)MM * DD];
__device__ float g_q   [(size_t)MM * DD];
__device__ float g_k   [(size_t)MM * DD];
__device__ float g_v   [(size_t)MM * DD];
__device__ float g_attn[(size_t)MM * DD];
__device__ float g_x   [(size_t)MM * DD];
__device__ float g_h   [(size_t)MM * MLP];

// ---------------- LayerNorm (D=1024, biased var, eps=1e-5) -------------
__global__ __launch_bounds__(256) void ln_kernel(
    const float* __restrict__ X, const float* __restrict__ w,
    const float* __restrict__ b, float* __restrict__ Y)
{
    const int row = blockIdx.x;
    const int tid = threadIdx.x;
    const float* x = X + (size_t)row * DD;

    float4 xv = *(const float4*)(x + tid * 4);
    float s  = xv.x + xv.y + xv.z + xv.w;
    float s2 = fmaf(xv.x, xv.x, fmaf(xv.y, xv.y, fmaf(xv.z, xv.z, xv.w * xv.w)));

    #pragma unroll
    for (int o = 16; o; o >>= 1) {
        s  += __shfl_xor_sync(0xFFFFFFFFu, s,  o);
        s2 += __shfl_xor_sync(0xFFFFFFFFu, s2, o);
    }
    __shared__ float sh[8], sh2[8];
    const int lane = tid & 31, wid = tid >> 5;
    if (lane == 0) { sh[wid] = s; sh2[wid] = s2; }
    __syncthreads();
    float S = 0.f, S2 = 0.f;
    #pragma unroll
    for (int i = 0; i < 8; i++) { S += sh[i]; S2 += sh2[i]; }

    const float mean = S * (1.0f / DD);
    const float var  = S2 * (1.0f / DD) - mean * mean;
    const float inv  = rsqrtf(var + 1e-5f);

    float4 wv = *(const float4*)(w + tid * 4);
    float4 bv = *(const float4*)(b + tid * 4);
    float4 y;
    y.x = (xv.x - mean) * inv * wv.x + bv.x;
    y.y = (xv.y - mean) * inv * wv.y + bv.y;
    y.z = (xv.z - mean) * inv * wv.z + bv.z;
    y.w = (xv.w - mean) * inv * wv.w + bv.w;
    *(float4*)(Y + (size_t)row * DD + tid * 4) = y;
}

// ---------------- generic tiled GEMM: C = A[M,K] @ W[K,N] + bias (+epi) --
// EPI: 0 = bias only, 1 = bias + residual R, 2 = bias + exact GELU
#define BM 128
#define BN 128
#define BK 16

template<int EPI>
__global__ __launch_bounds__(256) void gemm_kernel(
    const float* __restrict__ A, const float* __restrict__ W,
    const float* __restrict__ bias, const float* __restrict__ R,
    float* __restrict__ C, int M, int N, int K)
{
    __shared__ float As[BK][BM];   // A tile, transposed (k-major)
    __shared__ float Ws[BK][BN];   // W tile

    const int tid = threadIdx.x;
    const int bm = blockIdx.y * BM;
    const int bn = blockIdx.x * BN;

    const int a_row = tid >> 2;          // 0..63 (x2 iterations)
    const int a_col = (tid & 3) * 4;     // 0,4,8,12
    const int w_row = tid >> 5;          // 0..7 (x2 iterations)
    const int w_col = (tid & 31) * 4;    // 0..124

    const int ty = tid >> 4;             // 0..15
    const int tx = tid & 15;             // 0..15

    float acc[8][8];
    #pragma unroll
    for (int i = 0; i < 8; i++)
        #pragma unroll
        for (int j = 0; j < 8; j++) acc[i][j] = 0.f;

    for (int k0 = 0; k0 < K; k0 += BK) {
        #pragma unroll
        for (int r = 0; r < 2; r++) {
            const int row = a_row + r * 64;
            float4 v = *(const float4*)(A + (size_t)(bm + row) * K + k0 + a_col);
            As[a_col + 0][row] = v.x;
            As[a_col + 1][row] = v.y;
            As[a_col + 2][row] = v.z;
            As[a_col + 3][row] = v.w;
        }
        #pragma unroll
        for (int r = 0; r < 2; r++) {
            const int row = w_row + r * 8;
            *(float4*)&Ws[row][w_col] =
                *(const float4*)(W + (size_t)(k0 + row) * N + bn + w_col);
        }
        __syncthreads();

        #pragma unroll
        for (int kk = 0; kk < BK; kk++) {
            float a[8], b[8];
            *(float4*)(a + 0) = *(const float4*)&As[kk][ty * 8 + 0];
            *(float4*)(a + 4) = *(const float4*)&As[kk][ty * 8 + 4];
            *(float4*)(b + 0) = *(const float4*)&Ws[kk][tx * 8 + 0];
            *(float4*)(b + 4) = *(const float4*)&Ws[kk][tx * 8 + 4];
            #pragma unroll
            for (int i = 0; i < 8; i++)
                #pragma unroll
                for (int j = 0; j < 8; j++)
                    acc[i][j] = fmaf(a[i], b[j], acc[i][j]);
        }
        __syncthreads();
    }

    // epilogue
    #pragma unroll
    for (int i = 0; i < 8; i++) {
        const int row = bm + ty * 8 + i;
        float* crow = C + (size_t)row * N + bn + tx * 8;
        const float* rrow = (EPI == 1) ? (R + (size_t)row * N + bn + tx * 8) : nullptr;
        float out[8];
        #pragma unroll
        for (int j = 0; j < 8; j++) {
            float vv = acc[i][j] + bias[bn + tx * 8 + j];
            if (EPI == 1) vv += rrow[j];
            if (EPI == 2) vv = 0.5f * vv * (1.0f + erff(vv * 0.70710678118654752f));
            out[j] = vv;
        }
        *(float4*)(crow + 0) = *(float4*)(out + 0);
        *(float4*)(crow + 4) = *(float4*)(out + 4);
    }
}

// ---------------- fused per-token linear attention ----------------
// The reference einsums reduce over the HEAD axis per position:
//   kv[d,e]  = sum_h fk[h,d] * v[h,e]        (64x64 per token)
//   qkv[h,e] = sum_d fq[h,d] * kv[d,e]
//   qk[h]    = sum_d fq[h,d] * ksum[d],  out = qkv/(qk+1e-6)
// One CTA per token; everything fits in SMEM.
__device__ __forceinline__ float elu1(float x) {
    return x > 0.f ? x + 1.0f : expf(x);   // elu(x)+1
}

__global__ __launch_bounds__(256) void attn_kernel(
    const float* __restrict__ Q, const float* __restrict__ K_,
    const float* __restrict__ V, float* __restrict__ O)
{
    __shared__ float fq[HH][HD];
    __shared__ float fk[HH][HD];
    __shared__ float vv[HH][HD];
    __shared__ float kv[HD][HD];
    __shared__ float ksum[HD];

    const size_t base = (size_t)blockIdx.x * DD;
    const int tid = threadIdx.x;

    // load + transform (1024 floats each; 256 threads x float4)
    {
        float4 q4 = *(const float4*)(Q  + base + tid * 4);
        float4 k4 = *(const float4*)(K_ + base + tid * 4);
        float4 v4 = *(const float4*)(V  + base + tid * 4);
        float* fqf = &fq[0][0];
        float* fkf = &fk[0][0];
        float* vvf = &vv[0][0];
        fqf[tid*4+0] = elu1(q4.x); fqf[tid*4+1] = elu1(q4.y);
        fqf[tid*4+2] = elu1(q4.z); fqf[tid*4+3] = elu1(q4.w);
        fkf[tid*4+0] = elu1(k4.x); fkf[tid*4+1] = elu1(k4.y);
        fkf[tid*4+2] = elu1(k4.z); fkf[tid*4+3] = elu1(k4.w);
        vvf[tid*4+0] = v4.x; vvf[tid*4+1] = v4.y;
        vvf[tid*4+2] = v4.z; vvf[tid*4+3] = v4.w;
    }
    __syncthreads();

    // ksum[d] = sum_h fk[h][d]
    if (tid < HD) {
        float s = 0.f;
        #pragma unroll
        for (int h = 0; h < HH; h++) s += fk[h][tid];
        ksum[tid] = s;
    }

    // kv[d][e] = sum_h fk[h][d] * v[h][e]
    {
        const int e = tid & 63;
        const int d0 = tid >> 6;       // 0..3
        #pragma unroll
        for (int j = 0; j < 16; j++) {
            const int d = d0 + j * 4;
            float s = 0.f;
            #pragma unroll
            for (int h = 0; h < HH; h++) s = fmaf(fk[h][d], vv[h][e], s);
            kv[d][e] = s;
        }
    }
    __syncthreads();

    // qkv / qk
    {
        const int e = tid & 63;
        const int h0 = tid >> 6;       // 0..3
        #pragma unroll
        for (int j = 0; j < 4; j++) {
            const int h = h0 + j * 4;
            float s = 0.f, sq = 0.f;
            #pragma unroll
            for (int d = 0; d < HD; d++) {
                const float f = fq[h][d];
                s  = fmaf(f, kv[d][e], s);
                sq = fmaf(f, ksum[d], sq);
            }
            O[base + h * HD + e] = s / (sq + 1e-6f);
        }
    }
}

// ---------------- launch ----------------
extern "C" void kernel_launch(void* const* d_in, const int* in_sizes, int n_in,
                              void* d_out, int out_size)
{
    const float* q_x    = (const float*)d_in[0];
    const float* ln1_w  = (const float*)d_in[1];
    const float* ln1_b  = (const float*)d_in[2];
    const float* wq     = (const float*)d_in[3];
    const float* bq     = (const float*)d_in[4];
    const float* wk     = (const float*)d_in[5];
    const float* bk     = (const float*)d_in[6];
    const float* wv     = (const float*)d_in[7];
    const float* bv     = (const float*)d_in[8];
    const float* wo     = (const float*)d_in[9];
    const float* bo     = (const float*)d_in[10];
    const float* ln2_w  = (const float*)d_in[11];
    const float* ln2_b  = (const float*)d_in[12];
    const float* fc_w   = (const float*)d_in[13];
    const float* fc_b   = (const float*)d_in[14];
    const float* proj_w = (const float*)d_in[15];
    const float* proj_b = (const float*)d_in[16];
    float* out = (float*)d_out;

    float *p_xn, *p_q, *p_k, *p_v, *p_attn, *p_x, *p_h;
    cudaGetSymbolAddress((void**)&p_xn,   g_xn);
    cudaGetSymbolAddress((void**)&p_q,    g_q);
    cudaGetSymbolAddress((void**)&p_k,    g_k);
    cudaGetSymbolAddress((void**)&p_v,    g_v);
    cudaGetSymbolAddress((void**)&p_attn, g_attn);
    cudaGetSymbolAddress((void**)&p_x,    g_x);
    cudaGetSymbolAddress((void**)&p_h,    g_h);

    const dim3 gD (DD  / BN, MM / BM);   // (8, 128)
    const dim3 gML(MLP / BN, MM / BM);   // (32, 128)

    // 1) xn = LN1(q_x)
    ln_kernel<<<MM, 256>>>(q_x, ln1_w, ln1_b, p_xn);
    // 2) q/k/v = xn @ w* + b*
    gemm_kernel<0><<<gD, 256>>>(p_xn, wq, bq, nullptr, p_q, MM, DD, DD);
    gemm_kernel<0><<<gD, 256>>>(p_xn, wk, bk, nullptr, p_k, MM, DD, DD);
    gemm_kernel<0><<<gD, 256>>>(p_xn, wv, bv, nullptr, p_v, MM, DD, DD);
    // 3) fused per-token linear attention
    attn_kernel<<<MM, 256>>>(p_q, p_k, p_v, p_attn);
    // 4) x = q_x + attn @ wo + bo
    gemm_kernel<1><<<gD, 256>>>(p_attn, wo, bo, q_x, p_x, MM, DD, DD);
    // 5) xn2 = LN2(x)
    ln_kernel<<<MM, 256>>>(p_x, ln2_w, ln2_b, p_xn);
    // 6) h = gelu(xn2 @ fc_w + fc_b)
    gemm_kernel<2><<<gML, 256>>>(p_xn, fc_w, fc_b, nullptr, p_h, MM, MLP, DD);
    // 7) out = x + h @ proj_w + proj_b
    gemm_kernel<1><<<gD, 256>>>(p_h, proj_w, proj_b, p_x, out, MM, DD, MLP);
}

// round 4
// speedup vs baseline: 1.0028x; 1.0019x over previous
#include <cuda_runtime.h>
#include <math.h>

// ---------------- problem constants ----------------
#define BB 4
#define NN 4096
#define DD 1024
#define HH 16
#define HD 64
#define MLP 4096
#define MM (BB*NN)          // 16384 rows

// ---------------- scratch (device globals; no allocation allowed) ------
__device__ float g_xn  [(size_t)MM * DD];
__device__ float g_q   [(size_t)MM * DD];
__device__ float g_k   [(size_t)MM * DD];
__device__ float g_v   [(size_t)MM * DD];
__device__ float g_attn[(size_t)MM * DD];
__device__ float g_x   [(size_t)MM * DD];
__device__ float g_h   [(size_t)MM * MLP];

// ---------------- LayerNorm (D=1024, biased var, eps=1e-5) -------------
__global__ __launch_bounds__(256) void ln_kernel(
    const float* __restrict__ X, const float* __restrict__ w,
    const float* __restrict__ b, float* __restrict__ Y)
{
    const int row = blockIdx.x;
    const int tid = threadIdx.x;
    const float* x = X + (size_t)row * DD;

    float4 xv = *(const float4*)(x + tid * 4);
    float s  = xv.x + xv.y + xv.z + xv.w;
    float s2 = fmaf(xv.x, xv.x, fmaf(xv.y, xv.y, fmaf(xv.z, xv.z, xv.w * xv.w)));

    #pragma unroll
    for (int o = 16; o; o >>= 1) {
        s  += __shfl_xor_sync(0xFFFFFFFFu, s,  o);
        s2 += __shfl_xor_sync(0xFFFFFFFFu, s2, o);
    }
    __shared__ float sh[8], sh2[8];
    const int lane = tid & 31, wid = tid >> 5;
    if (lane == 0) { sh[wid] = s; sh2[wid] = s2; }
    __syncthreads();
    float S = 0.f, S2 = 0.f;
    #pragma unroll
    for (int i = 0; i < 8; i++) { S += sh[i]; S2 += sh2[i]; }

    const float mean = S * (1.0f / DD);
    const float var  = S2 * (1.0f / DD) - mean * mean;
    const float inv  = rsqrtf(var + 1e-5f);

    float4 wv = *(const float4*)(w + tid * 4);
    float4 bv = *(const float4*)(b + tid * 4);
    float4 y;
    y.x = (xv.x - mean) * inv * wv.x + bv.x;
    y.y = (xv.y - mean) * inv * wv.y + bv.y;
    y.z = (xv.z - mean) * inv * wv.z + bv.z;
    y.w = (xv.w - mean) * inv * wv.w + bv.w;
    *(float4*)(Y + (size_t)row * DD + tid * 4) = y;
}

// ---------------- generic tiled GEMM: C = A[M,K] @ W[K,N] + bias (+epi) --
// EPI: 0 = bias only, 1 = bias + residual R, 2 = bias + exact GELU
#define BM 128
#define BN 128
#define BK 16

template<int EPI>
__global__ __launch_bounds__(256) void gemm_kernel(
    const float* __restrict__ A, const float* __restrict__ W,
    const float* __restrict__ bias, const float* __restrict__ R,
    float* __restrict__ C, int M, int N, int K)
{
    __shared__ float As[BK][BM];   // A tile, transposed (k-major)
    __shared__ float Ws[BK][BN];   // W tile

    const int tid = threadIdx.x;
    const int bm = blockIdx.y * BM;
    const int bn = blockIdx.x * BN;

    const int a_row = tid >> 2;          // 0..63 (x2 iterations)
    const int a_col = (tid & 3) * 4;     // 0,4,8,12
    const int w_row = tid >> 5;          // 0..7 (x2 iterations)
    const int w_col = (tid & 31) * 4;    // 0..124

    const int ty = tid >> 4;             // 0..15
    const int tx = tid & 15;             // 0..15

    float acc[8][8];
    #pragma unroll
    for (int i = 0; i < 8; i++)
        #pragma unroll
        for (int j = 0; j < 8; j++) acc[i][j] = 0.f;

    for (int k0 = 0; k0 < K; k0 += BK) {
        #pragma unroll
        for (int r = 0; r < 2; r++) {
            const int row = a_row + r * 64;
            float4 v = *(const float4*)(A + (size_t)(bm + row) * K + k0 + a_col);
            As[a_col + 0][row] = v.x;
            As[a_col + 1][row] = v.y;
            As[a_col + 2][row] = v.z;
            As[a_col + 3][row] = v.w;
        }
        #pragma unroll
        for (int r = 0; r < 2; r++) {
            const int row = w_row + r * 8;
            *(float4*)&Ws[row][w_col] =
                *(const float4*)(W + (size_t)(k0 + row) * N + bn + w_col);
        }
        __syncthreads();

        #pragma unroll
        for (int kk = 0; kk < BK; kk++) {
            float a[8], b[8];
            *(float4*)(a + 0) = *(const float4*)&As[kk][ty * 8 + 0];
            *(float4*)(a + 4) = *(const float4*)&As[kk][ty * 8 + 4];
            *(float4*)(b + 0) = *(const float4*)&Ws[kk][tx * 8 + 0];
            *(float4*)(b + 4) = *(const float4*)&Ws[kk][tx * 8 + 4];
            #pragma unroll
            for (int i = 0; i < 8; i++)
                #pragma unroll
                for (int j = 0; j < 8; j++)
                    acc[i][j] = fmaf(a[i], b[j], acc[i][j]);
        }
        __syncthreads();
    }

    // epilogue
    #pragma unroll
    for (int i = 0; i < 8; i++) {
        const int row = bm + ty * 8 + i;
        float* crow = C + (size_t)row * N + bn + tx * 8;
        const float* rrow = (EPI == 1) ? (R + (size_t)row * N + bn + tx * 8) : nullptr;
        float out[8];
        #pragma unroll
        for (int j = 0; j < 8; j++) {
            float vv = acc[i][j] + bias[bn + tx * 8 + j];
            if (EPI == 1) vv += rrow[j];
            if (EPI == 2) vv = 0.5f * vv * (1.0f + erff(vv * 0.70710678118654752f));
            out[j] = vv;
        }
        *(float4*)(crow + 0) = *(float4*)(out + 0);
        *(float4*)(crow + 4) = *(float4*)(out + 4);
    }
}

// ---------------- fused per-token linear attention ----------------
// The reference einsums reduce over the HEAD axis per position:
//   kv[d,e]  = sum_h fk[h,d] * v[h,e]        (64x64 per token)
//   qkv[h,e] = sum_d fq[h,d] * kv[d,e]
//   qk[h]    = sum_d fq[h,d] * ksum[d],  out = qkv/(qk+1e-6)
// One CTA per token; everything fits in SMEM.
__device__ __forceinline__ float elu1(float x) {
    return x > 0.f ? x + 1.0f : expf(x);   // elu(x)+1
}

__global__ __launch_bounds__(256) void attn_kernel(
    const float* __restrict__ Q, const float* __restrict__ K_,
    const float* __restrict__ V, float* __restrict__ O)
{
    __shared__ float fq[HH][HD];
    __shared__ float fk[HH][HD];
    __shared__ float vv[HH][HD];
    __shared__ float kv[HD][HD];
    __shared__ float ksum[HD];

    const size_t base = (size_t)blockIdx.x * DD;
    const int tid = threadIdx.x;

    // load + transform (1024 floats each; 256 threads x float4)
    {
        float4 q4 = *(const float4*)(Q  + base + tid * 4);
        float4 k4 = *(const float4*)(K_ + base + tid * 4);
        float4 v4 = *(const float4*)(V  + base + tid * 4);
        float* fqf = &fq[0][0];
        float* fkf = &fk[0][0];
        float* vvf = &vv[0][0];
        fqf[tid*4+0] = elu1(q4.x); fqf[tid*4+1] = elu1(q4.y);
        fqf[tid*4+2] = elu1(q4.z); fqf[tid*4+3] = elu1(q4.w);
        fkf[tid*4+0] = elu1(k4.x); fkf[tid*4+1] = elu1(k4.y);
        fkf[tid*4+2] = elu1(k4.z); fkf[tid*4+3] = elu1(k4.w);
        vvf[tid*4+0] = v4.x; vvf[tid*4+1] = v4.y;
        vvf[tid*4+2] = v4.z; vvf[tid*4+3] = v4.w;
    }
    __syncthreads();

    // ksum[d] = sum_h fk[h][d]
    if (tid < HD) {
        float s = 0.f;
        #pragma unroll
        for (int h = 0; h < HH; h++) s += fk[h][tid];
        ksum[tid] = s;
    }

    // kv[d][e] = sum_h fk[h][d] * v[h][e]
    {
        const int e = tid & 63;
        const int d0 = tid >> 6;       // 0..3
        #pragma unroll
        for (int j = 0; j < 16; j++) {
            const int d = d0 + j * 4;
            float s = 0.f;
            #pragma unroll
            for (int h = 0; h < HH; h++) s = fmaf(fk[h][d], vv[h][e], s);
            kv[d][e] = s;
        }
    }
    __syncthreads();

    // qkv / qk
    {
        const int e = tid & 63;
        const int h0 = tid >> 6;       // 0..3
        #pragma unroll
        for (int j = 0; j < 4; j++) {
            const int h = h0 + j * 4;
            float s = 0.f, sq = 0.f;
            #pragma unroll
            for (int d = 0; d < HD; d++) {
                const float f = fq[h][d];
                s  = fmaf(f, kv[d][e], s);
                sq = fmaf(f, ksum[d], sq);
            }
            O[base + h * HD + e] = s / (sq + 1e-6f);
        }
    }
}

// ---------------- launch ----------------
extern "C" void kernel_launch(void* const* d_in, const int* in_sizes, int n_in,
                              void* d_out, int out_size)
{
    const float* q_x    = (const float*)d_in[0];
    const float* ln1_w  = (const float*)d_in[1];
    const float* ln1_b  = (const float*)d_in[2];
    const float* wq     = (const float*)d_in[3];
    const float* bq     = (const float*)d_in[4];
    const float* wk     = (const float*)d_in[5];
    const float* bk     = (const float*)d_in[6];
    const float* wv     = (const float*)d_in[7];
    const float* bv     = (const float*)d_in[8];
    const float* wo     = (const float*)d_in[9];
    const float* bo     = (const float*)d_in[10];
    const float* ln2_w  = (const float*)d_in[11];
    const float* ln2_b  = (const float*)d_in[12];
    const float* fc_w   = (const float*)d_in[13];
    const float* fc_b   = (const float*)d_in[14];
    const float* proj_w = (const float*)d_in[15];
    const float* proj_b = (const float*)d_in[16];
    float* out = (float*)d_out;

    float *p_xn, *p_q, *p_k, *p_v, *p_attn, *p_x, *p_h;
    cudaGetSymbolAddress((void**)&p_xn,   g_xn);
    cudaGetSymbolAddress((void**)&p_q,    g_q);
    cudaGetSymbolAddress((void**)&p_k,    g_k);
    cudaGetSymbolAddress((void**)&p_v,    g_v);
    cudaGetSymbolAddress((void**)&p_attn, g_attn);
    cudaGetSymbolAddress((void**)&p_x,    g_x);
    cudaGetSymbolAddress((void**)&p_h,    g_h);

    const dim3 gD (DD  / BN, MM / BM);   // (8, 128)
    const dim3 gML(MLP / BN, MM / BM);   // (32, 128)

    // 1) xn = LN1(q_x)
    ln_kernel<<<MM, 256>>>(q_x, ln1_w, ln1_b, p_xn);
    // 2) q/k/v = xn @ w* + b*
    gemm_kernel<0><<<gD, 256>>>(p_xn, wq, bq, nullptr, p_q, MM, DD, DD);
    gemm_kernel<0><<<gD, 256>>>(p_xn, wk, bk, nullptr, p_k, MM, DD, DD);
    gemm_kernel<0><<<gD, 256>>>(p_xn, wv, bv, nullptr, p_v, MM, DD, DD);
    // 3) fused per-token linear attention
    attn_kernel<<<MM, 256>>>(p_q, p_k, p_v, p_attn);
    // 4) x = q_x + attn @ wo + bo
    gemm_kernel<1><<<gD, 256>>>(p_attn, wo, bo, q_x, p_x, MM, DD, DD);
    // 5) xn2 = LN2(x)
    ln_kernel<<<MM, 256>>>(p_x, ln2_w, ln2_b, p_xn);
    // 6) h = gelu(xn2 @ fc_w + fc_b)
    gemm_kernel<2><<<gML, 256>>>(p_xn, fc_w, fc_b, nullptr, p_h, MM, MLP, DD);
    // 7) out = x + h @ proj_w + proj_b
    gemm_kernel<1><<<gD, 256>>>(p_h, proj_w, proj_b, p_x, out, MM, DD, MLP);
}